// round 16
// baseline (speedup 1.0000x reference)
#include <cuda_runtime.h>
#include <math.h>

// Beran estimator: C=16, B=256, K=8, N=8192.
// Kernel 1: pack 16 labels -> 8 pair-indices (uint2) per element.
// Kernel 2: one CTA per batch row, 512 threads = 16 warps; warp w owns span
//           [w*512,(w+1)*512). float4 granularity: lane owns 4 consecutive
//           elements/round, 4 rounds. One 5-SHFL warp scan per 128 elements.
//           steps normalization via telescoping: sum(steps) = 1 - exp(-h_total),
//           so surv + steps are produced in ONE fused loop.

#define CC 16
#define BB 256
#define KK 8
#define NN 8192
#define THREADS 512
#define NWARPS (THREADS / 32)   // 16
#define SPAN (NN / NWARPS)      // 512 elements per warp
#define ROUNDS4 4               // 4 rounds x 128 elements (4 per lane)

#define ISCLOSE_TOL (1e-8f + 1e-5f)
#define EPS_GUARD 1e-13f

__device__ uint2 g_packed[NN];   // 64 KB: 8 pair-bytes per element

// ---------------------------------------------------------------- pack kernel
__global__ void pack_kernel(const int* __restrict__ c_in)
{
    const int n = blockIdx.x * blockDim.x + threadIdx.x;
    if (n >= NN) return;
    const int4* cr = (const int4*)(c_in + n * CC);
    int4 a = cr[0], b = cr[1], c = cr[2], d = cr[3];
    unsigned lo = (unsigned)(a.x * 8 + a.y)
                | ((unsigned)(a.z * 8 + a.w) << 8)
                | ((unsigned)(b.x * 8 + b.y) << 16)
                | ((unsigned)(b.z * 8 + b.w) << 24);
    unsigned hi = (unsigned)(c.x * 8 + c.y)
                | ((unsigned)(c.z * 8 + c.w) << 8)
                | ((unsigned)(d.x * 8 + d.y) << 16)
                | ((unsigned)(d.z * 8 + d.w) << 24);
    g_packed[n] = make_uint2(lo, hi);
}

// ------------------------------------------------------------------- helpers
__device__ __forceinline__ float warp_incl_scan(float x, int lane)
{
    #pragma unroll
    for (int o = 1; o < 32; o <<= 1) {
        float y = __shfl_up_sync(0xffffffffu, x, o);
        if (lane >= o) x += y;
    }
    return x;
}

// Per-warp value -> (exclusive offset among warps, block total). 2 barriers.
__device__ __forceinline__ void block_combine(float wtot, int lane, int wid,
                                              float* wsum, float& off, float& tot)
{
    if (lane == 0) wsum[wid] = wtot;
    __syncthreads();
    off = 0.0f; tot = 0.0f;
    #pragma unroll
    for (int j = 0; j < NWARPS; j++) {
        float v = wsum[j];          // broadcast LDS, conflict-free
        tot += v;
        off += (j < wid) ? v : 0.0f;
    }
    __syncthreads();                // wsum reusable afterwards
}

// 8 pair-table lookups for one element
__device__ __forceinline__ float gather8(const float* tab, unsigned lo, unsigned hi)
{
    return tab[  0 + ( lo        & 0xFF)]
         + tab[ 64 + ((lo >> 8)  & 0xFF)]
         + tab[128 + ((lo >> 16) & 0xFF)]
         + tab[192 + ( lo >> 24        )]
         + tab[256 + ( hi        & 0xFF)]
         + tab[320 + ((hi >> 8)  & 0xFF)]
         + tab[384 + ((hi >> 16) & 0xFF)]
         + tab[448 + ( hi >> 24        )];
}

// xi for one element from exclusive/inclusive weight-cumsum (unnormalized)
__device__ __forceinline__ float xi_elem(float excl, float incl,
                                         float inv_s, float delta)
{
    float shifted = excl * inv_s;
    float wc      = incl * inv_s;
    bool bad = (fabsf(shifted - 1.0f) <= ISCLOSE_TOL) ||
               (fabsf(wc      - 1.0f) <= ISCLOSE_TOL);
    if (bad) { shifted = 0.0f; wc = 0.0f; }
    return delta * (__logf(1.0f - shifted) - __logf(1.0f - wc));
}

// ---------------------------------------------------------------- main kernel
__global__ __launch_bounds__(THREADS, 2)
void beran_kernel(const float* __restrict__ c_p,
                  const float* __restrict__ delta_in,
                  const float* __restrict__ bandwidth,
                  float*       __restrict__ out)   // [surv(B*N) | steps(B*N)]
{
    __shared__ float p_sh[CC * KK];     // softmax table (128 floats)
    __shared__ float sq_sh[CC];
    __shared__ float tab[8 * 64];       // pairwise sums tab[p][l1*8+l2]
    __shared__ float wsum[NWARPS];

    const int b      = blockIdx.x;
    const int t      = threadIdx.x;
    const int lane   = t & 31;
    const int wid    = t >> 5;
    const int nbase4 = wid * SPAN + lane * 4;   // round i covers nbase4 + i*128 .. +3

    // ---- Phase 0: softmax per concept + sumsq (precise expf; cold path) ----
    if (t < CC) {
        const float* row = c_p + (t * BB + b) * KK;
        float v[KK];
        float mx = -INFINITY;
        #pragma unroll
        for (int k = 0; k < KK; k++) { v[k] = row[k]; mx = fmaxf(mx, v[k]); }
        float sm = 0.0f;
        #pragma unroll
        for (int k = 0; k < KK; k++) { v[k] = expf(v[k] - mx); sm += v[k]; }
        float inv = 1.0f / sm;
        float ss = 0.0f;
        #pragma unroll
        for (int k = 0; k < KK; k++) {
            float p = v[k] * inv;
            p_sh[t * KK + k] = p;
            ss += p * p;
        }
        sq_sh[t] = ss;
    }
    __syncthreads();

    // pair tables (one entry per thread) + per-thread S, inv_bw
    {
        const int p   = t >> 6;
        const int idx = t & 63;
        tab[t] = p_sh[(2 * p) * KK + (idx >> 3)] + p_sh[(2 * p + 1) * KK + (idx & 7)];
    }
    float S = (float)CC;
    #pragma unroll
    for (int c = 0; c < CC; c++) S += sq_sh[c];   // broadcast LDS
    const float bwv    = fminf(fmaxf(bandwidth[0], 0.1f), 10.0f);
    const float inv_bw = 1.0f / bwv;
    __syncthreads();   // tab visible

    // ---- Phase A: weights (4 elements/lane/round) ----
    float4 buf[ROUNDS4];     // reused: w -> filtered_xi
    float lsum = 0.0f;
    #pragma unroll
    for (int i = 0; i < ROUNDS4; i++) {
        const int e = nbase4 + i * 128;
        uint4 pa = *(const uint4*)(g_packed + e);       // elems e, e+1
        uint4 pb = *(const uint4*)(g_packed + e + 2);   // elems e+2, e+3
        float4 w;
        w.x = __expf((2.0f * gather8(tab, pa.x, pa.y) - S) * inv_bw);
        w.y = __expf((2.0f * gather8(tab, pa.z, pa.w) - S) * inv_bw);
        w.z = __expf((2.0f * gather8(tab, pb.x, pb.y) - S) * inv_bw);
        w.w = __expf((2.0f * gather8(tab, pb.z, pb.w) - S) * inv_bw);
        buf[i] = w;
        lsum += (w.x + w.y) + (w.z + w.w);
    }

    // total of weights -> block combine
    float wtot = __shfl_sync(0xffffffffu, warp_incl_scan(lsum, lane), 31);
    float w_off, s_total;
    block_combine(wtot, lane, wid, wsum, w_off, s_total);
    const float inv_s = (s_total < EPS_GUARD) ? 0.0f : (1.0f / s_total);

    // ---- Scan 1: weights cumsum -> xi -> filtered_xi ----
    float carry = 0.0f;
    float hsum  = 0.0f;
    #pragma unroll
    for (int i = 0; i < ROUNDS4; i++) {
        const int e = nbase4 + i * 128;
        float4 w = buf[i];
        float tsum = (w.x + w.y) + (w.z + w.w);
        float incl = warp_incl_scan(tsum, lane);
        float base = w_off + carry + (incl - tsum);   // excl prefix at lane block
        carry += __shfl_sync(0xffffffffu, incl, 31);
        float p1 = base + w.x;
        float p2 = p1 + w.y;
        float p3 = p2 + w.z;
        float p4 = p3 + w.w;
        float4 dv = *(const float4*)(delta_in + e);   // coalesced 16B
        float4 f;
        f.x = xi_elem(base, p1, inv_s, dv.x);
        f.y = xi_elem(p1,   p2, inv_s, dv.y);
        f.z = xi_elem(p2,   p3, inv_s, dv.z);
        f.w = xi_elem(p3,   p4, inv_s, dv.w);
        buf[i] = f;
        hsum += (f.x + f.y) + (f.z + f.w);
    }

    // ---- Scan 2 combine ----
    float htot = __shfl_sync(0xffffffffu, warp_incl_scan(hsum, lane), 31);
    float h_off, h_total;
    block_combine(htot, lane, wid, wsum, h_off, h_total);

    // steps normalization factor via telescoping: sum(steps) = 1 - exp(-h_total)
    const float s2_total = 1.0f - __expf(-h_total);
    const float inv_s2   = (s2_total < EPS_GUARD) ? 0.0f : (1.0f / s2_total);

    float* out_surv  = out + (size_t)b * NN;
    float* out_steps = out + (size_t)BB * NN + (size_t)b * NN;

    // ---- Fused hazard cumsum -> surv + normalized steps ----
    float hcarry    = 0.0f;
    float prev_last = __expf(-h_off);   // surv just before this warp's span
    #pragma unroll
    for (int i = 0; i < ROUNDS4; i++) {
        const int e = nbase4 + i * 128;
        float4 f = buf[i];
        float tsum = (f.x + f.y) + (f.z + f.w);
        float incl = warp_incl_scan(tsum, lane);
        float base = h_off + hcarry + (incl - tsum);
        hcarry += __shfl_sync(0xffffffffu, incl, 31);
        float h1 = base + f.x;
        float h2 = h1 + f.y;
        float h3 = h2 + f.z;
        float h4 = h3 + f.w;
        float4 sv;
        sv.x = __expf(-h1);
        sv.y = __expf(-h2);
        sv.z = __expf(-h3);
        sv.w = __expf(-h4);
        __stcg((float4*)(out_surv + e), sv);          // coalesced 16B streaming
        float pv = __shfl_up_sync(0xffffffffu, sv.w, 1);
        if (lane == 0) pv = prev_last;
        prev_last = __shfl_sync(0xffffffffu, sv.w, 31);
        float4 st;
        st.x = (pv   - sv.x) * inv_s2;                // steps[0] = 1 - surv[0] falls out
        st.y = (sv.x - sv.y) * inv_s2;
        st.z = (sv.y - sv.z) * inv_s2;
        st.w = (sv.z - sv.w) * inv_s2;
        __stcg((float4*)(out_steps + e), st);         // coalesced 16B streaming
    }
}

extern "C" void kernel_launch(void* const* d_in, const int* in_sizes, int n_in,
                              void* d_out, int out_size)
{
    const float* c_p       = (const float*)d_in[0];
    const int*   c_in      = (const int*)  d_in[1];
    const float* delta_in  = (const float*)d_in[2];
    const float* bandwidth = (const float*)d_in[3];
    float* out = (float*)d_out;

    pack_kernel<<<NN / 256, 256>>>(c_in);
    beran_kernel<<<BB, THREADS>>>(c_p, delta_in, bandwidth, out);
}

// round 17
// speedup vs baseline: 1.0135x; 1.0135x over previous
#include <cuda_runtime.h>
#include <math.h>

// Beran estimator: C=16, B=256, K=8, N=8192.
// Kernel 1: pack 16 labels -> 8 pair-indices (uint2) per element.
// Kernel 2: one CTA per batch row, 512 threads = 16 warps; warp w owns span
//           [w*512,(w+1)*512), float4-granular lane ownership (4 consecutive
//           elems/lane/round, 4 rounds). ILP restructure: per pass, all 4
//           round scans run as independent pipelined SHFL chains (no carry
//           serialization); prev-surv recomputed as exp(-prefix) (no shfl
//           chain). steps normalization via telescoping sum = 1-exp(-h_total).

#define CC 16
#define BB 256
#define KK 8
#define NN 8192
#define THREADS 512
#define NWARPS (THREADS / 32)   // 16
#define SPAN (NN / NWARPS)      // 512 elements per warp
#define ROUNDS4 4               // 4 rounds x 128 elements (4 per lane)

#define ISCLOSE_TOL (1e-8f + 1e-5f)
#define EPS_GUARD 1e-13f

__device__ uint2 g_packed[NN];   // 64 KB: 8 pair-bytes per element

// ---------------------------------------------------------------- pack kernel
__global__ void pack_kernel(const int* __restrict__ c_in)
{
    const int n = blockIdx.x * blockDim.x + threadIdx.x;
    if (n >= NN) return;
    const int4* cr = (const int4*)(c_in + n * CC);
    int4 a = cr[0], b = cr[1], c = cr[2], d = cr[3];
    unsigned lo = (unsigned)(a.x * 8 + a.y)
                | ((unsigned)(a.z * 8 + a.w) << 8)
                | ((unsigned)(b.x * 8 + b.y) << 16)
                | ((unsigned)(b.z * 8 + b.w) << 24);
    unsigned hi = (unsigned)(c.x * 8 + c.y)
                | ((unsigned)(c.z * 8 + c.w) << 8)
                | ((unsigned)(d.x * 8 + d.y) << 16)
                | ((unsigned)(d.z * 8 + d.w) << 24);
    g_packed[n] = make_uint2(lo, hi);
}

// ------------------------------------------------------------------- helpers
__device__ __forceinline__ float warp_incl_scan(float x, int lane)
{
    #pragma unroll
    for (int o = 1; o < 32; o <<= 1) {
        float y = __shfl_up_sync(0xffffffffu, x, o);
        if (lane >= o) x += y;
    }
    return x;
}

// Per-warp value -> (exclusive offset among warps, block total). 1 barrier
// (dedicated buffer per call site; written once, then read-only).
__device__ __forceinline__ void block_combine(float wtot, int lane, int wid,
                                              float* wsum, float& off, float& tot)
{
    if (lane == 0) wsum[wid] = wtot;
    __syncthreads();
    off = 0.0f; tot = 0.0f;
    #pragma unroll
    for (int j = 0; j < NWARPS; j++) {
        float v = wsum[j];          // broadcast LDS, conflict-free
        tot += v;
        off += (j < wid) ? v : 0.0f;
    }
}

// 8 pair-table lookups for one element
__device__ __forceinline__ float gather8(const float* tab, unsigned lo, unsigned hi)
{
    return tab[  0 + ( lo        & 0xFF)]
         + tab[ 64 + ((lo >> 8)  & 0xFF)]
         + tab[128 + ((lo >> 16) & 0xFF)]
         + tab[192 + ( lo >> 24        )]
         + tab[256 + ( hi        & 0xFF)]
         + tab[320 + ((hi >> 8)  & 0xFF)]
         + tab[384 + ((hi >> 16) & 0xFF)]
         + tab[448 + ( hi >> 24        )];
}

// xi for one element from exclusive/inclusive weight-cumsum (unnormalized)
__device__ __forceinline__ float xi_elem(float excl, float incl,
                                         float inv_s, float delta)
{
    float shifted = excl * inv_s;
    float wc      = incl * inv_s;
    bool bad = (fabsf(shifted - 1.0f) <= ISCLOSE_TOL) ||
               (fabsf(wc      - 1.0f) <= ISCLOSE_TOL);
    if (bad) { shifted = 0.0f; wc = 0.0f; }
    return delta * (__logf(1.0f - shifted) - __logf(1.0f - wc));
}

// ---------------------------------------------------------------- main kernel
__global__ __launch_bounds__(THREADS, 2)
void beran_kernel(const float* __restrict__ c_p,
                  const float* __restrict__ delta_in,
                  const float* __restrict__ bandwidth,
                  float*       __restrict__ out)   // [surv(B*N) | steps(B*N)]
{
    __shared__ float p_sh[CC * KK];     // softmax table (128 floats)
    __shared__ float sq_sh[CC];
    __shared__ float tab[8 * 64];       // pairwise sums tab[p][l1*8+l2]
    __shared__ float wsumA[NWARPS];     // combine buffer: weights
    __shared__ float wsumB[NWARPS];     // combine buffer: hazards

    const int b      = blockIdx.x;
    const int t      = threadIdx.x;
    const int lane   = t & 31;
    const int wid    = t >> 5;
    const int nbase4 = wid * SPAN + lane * 4;   // round i covers nbase4 + i*128 .. +3

    // ---- Phase 0: softmax per concept + sumsq (precise expf; cold path) ----
    if (t < CC) {
        const float* row = c_p + (t * BB + b) * KK;
        float v[KK];
        float mx = -INFINITY;
        #pragma unroll
        for (int k = 0; k < KK; k++) { v[k] = row[k]; mx = fmaxf(mx, v[k]); }
        float sm = 0.0f;
        #pragma unroll
        for (int k = 0; k < KK; k++) { v[k] = expf(v[k] - mx); sm += v[k]; }
        float inv = 1.0f / sm;
        float ss = 0.0f;
        #pragma unroll
        for (int k = 0; k < KK; k++) {
            float p = v[k] * inv;
            p_sh[t * KK + k] = p;
            ss += p * p;
        }
        sq_sh[t] = ss;
    }
    __syncthreads();

    // pair tables (one entry per thread) + per-thread S, inv_bw
    {
        const int p   = t >> 6;
        const int idx = t & 63;
        tab[t] = p_sh[(2 * p) * KK + (idx >> 3)] + p_sh[(2 * p + 1) * KK + (idx & 7)];
    }
    float S = (float)CC;
    #pragma unroll
    for (int c = 0; c < CC; c++) S += sq_sh[c];   // broadcast LDS
    const float bwv    = fminf(fmaxf(bandwidth[0], 0.1f), 10.0f);
    const float inv_bw = 1.0f / bwv;
    __syncthreads();   // tab visible

    // ---- Phase A: weights (4 elements/lane/round, all independent) ----
    float4 buf[ROUNDS4];     // reused: w -> filtered_xi
    float lsum = 0.0f;
    #pragma unroll
    for (int i = 0; i < ROUNDS4; i++) {
        const int e = nbase4 + i * 128;
        uint4 pa = *(const uint4*)(g_packed + e);       // elems e, e+1
        uint4 pb = *(const uint4*)(g_packed + e + 2);   // elems e+2, e+3
        float4 w;
        w.x = __expf((2.0f * gather8(tab, pa.x, pa.y) - S) * inv_bw);
        w.y = __expf((2.0f * gather8(tab, pa.z, pa.w) - S) * inv_bw);
        w.z = __expf((2.0f * gather8(tab, pb.x, pb.y) - S) * inv_bw);
        w.w = __expf((2.0f * gather8(tab, pb.z, pb.w) - S) * inv_bw);
        buf[i] = w;
        lsum += (w.x + w.y) + (w.z + w.w);
    }

    // total of weights -> block combine
    float wtot = __shfl_sync(0xffffffffu, warp_incl_scan(lsum, lane), 31);
    float w_off, s_total;
    block_combine(wtot, lane, wid, wsumA, w_off, s_total);
    const float inv_s = (s_total < EPS_GUARD) ? 0.0f : (1.0f / s_total);

    // ---- Scan 1: weights cumsum -> xi -> filtered_xi ----
    // Independent per-round scans (pipelined SHFL chains), bases from totals.
    {
        float tsum[ROUNDS4], incl[ROUNDS4], rt[ROUNDS4];
        #pragma unroll
        for (int i = 0; i < ROUNDS4; i++) {
            float4 w = buf[i];
            tsum[i] = (w.x + w.y) + (w.z + w.w);
        }
        #pragma unroll
        for (int i = 0; i < ROUNDS4; i++) incl[i] = warp_incl_scan(tsum[i], lane);
        #pragma unroll
        for (int i = 0; i < ROUNDS4; i++)
            rt[i] = __shfl_sync(0xffffffffu, incl[i], 31);

        float hsum = 0.0f;
        float rbase = w_off;
        #pragma unroll
        for (int i = 0; i < ROUNDS4; i++) {
            const int e = nbase4 + i * 128;
            float4 w = buf[i];
            float base = rbase + (incl[i] - tsum[i]);
            rbase += rt[i];
            float p1 = base + w.x;
            float p2 = p1 + w.y;
            float p3 = p2 + w.z;
            float p4 = p3 + w.w;
            float4 dv = *(const float4*)(delta_in + e);   // coalesced 16B
            float4 f;
            f.x = xi_elem(base, p1, inv_s, dv.x);
            f.y = xi_elem(p1,   p2, inv_s, dv.y);
            f.z = xi_elem(p2,   p3, inv_s, dv.z);
            f.w = xi_elem(p3,   p4, inv_s, dv.w);
            buf[i] = f;
            hsum += (f.x + f.y) + (f.z + f.w);
        }

        // stash warp-total of hazards for pass 2 (reuse lsum slot)
        lsum = __shfl_sync(0xffffffffu, warp_incl_scan(hsum, lane), 31);
    }

    // ---- Scan 2 combine ----
    float h_off, h_total;
    block_combine(lsum, lane, wid, wsumB, h_off, h_total);

    // steps normalization factor via telescoping: sum(steps) = 1 - exp(-h_total)
    const float s2_total = 1.0f - __expf(-h_total);
    const float inv_s2   = (s2_total < EPS_GUARD) ? 0.0f : (1.0f / s2_total);

    float* out_surv  = out + (size_t)b * NN;
    float* out_steps = out + (size_t)BB * NN + (size_t)b * NN;

    // ---- Fused hazard cumsum -> surv + normalized steps ----
    {
        float tsum[ROUNDS4], incl[ROUNDS4], rt[ROUNDS4];
        #pragma unroll
        for (int i = 0; i < ROUNDS4; i++) {
            float4 f = buf[i];
            tsum[i] = (f.x + f.y) + (f.z + f.w);
        }
        #pragma unroll
        for (int i = 0; i < ROUNDS4; i++) incl[i] = warp_incl_scan(tsum[i], lane);
        #pragma unroll
        for (int i = 0; i < ROUNDS4; i++)
            rt[i] = __shfl_sync(0xffffffffu, incl[i], 31);

        float rbase = h_off;
        #pragma unroll
        for (int i = 0; i < ROUNDS4; i++) {
            const int e = nbase4 + i * 128;
            float4 f = buf[i];
            float base = rbase + (incl[i] - tsum[i]);   // excl hazard prefix
            rbase += rt[i];
            float h1 = base + f.x;
            float h2 = h1 + f.y;
            float h3 = h2 + f.z;
            float h4 = h3 + f.w;
            float pv = __expf(-base);   // surv of previous element (==1 at n=0)
            float4 sv;
            sv.x = __expf(-h1);
            sv.y = __expf(-h2);
            sv.z = __expf(-h3);
            sv.w = __expf(-h4);
            __stcg((float4*)(out_surv + e), sv);          // coalesced 16B streaming
            float4 st;
            st.x = (pv   - sv.x) * inv_s2;                // steps[0] = 1 - surv[0]
            st.y = (sv.x - sv.y) * inv_s2;
            st.z = (sv.y - sv.z) * inv_s2;
            st.w = (sv.z - sv.w) * inv_s2;
            __stcg((float4*)(out_steps + e), st);         // coalesced 16B streaming
        }
    }
}

extern "C" void kernel_launch(void* const* d_in, const int* in_sizes, int n_in,
                              void* d_out, int out_size)
{
    const float* c_p       = (const float*)d_in[0];
    const int*   c_in      = (const int*)  d_in[1];
    const float* delta_in  = (const float*)d_in[2];
    const float* bandwidth = (const float*)d_in[3];
    float* out = (float*)d_out;

    pack_kernel<<<NN / 256, 256>>>(c_in);
    beran_kernel<<<BB, THREADS>>>(c_p, delta_in, bandwidth, out);
}